// round 10
// baseline (speedup 1.0000x reference)
#include <cuda_runtime.h>
#include <cuda_fp16.h>

#define NN 100000
#define NE 3200000
#define H  64
#define SCAN_B 1024
#define NB 98                      // ceil(NN / SCAN_B)

// -------- device scratch (no allocations allowed) --------
__device__ int    g_cnt[NN];
__device__ int    g_row[NN + 1];
__device__ int    g_pos[NN];
__device__ float  g_dis[NN];
__device__ unsigned long long g_look[NB];   // lookback: status(2b)<<62 | value
__device__ int2   g_e[NE];          // CSR slot: (src, bitcast weight)
__device__ float4 g_ax[NN];         // aggregated layer-1 input (4-dim, fp32)
__device__ __half g_Ph[NN * H];     // fp16: h2 @ Wm1[0:64] + bm1
__device__ __half g_Qh[NN * H];     // fp16: h2 @ Wm1[64:128]

// -------- 1: histogram of in-degrees --------
__global__ void k_hist(const int* __restrict__ dst) {
    int e = blockIdx.x * blockDim.x + threadIdx.x;
    if (e < NE) atomicAdd(&g_cnt[dst[e]], 1);
}

// -------- 2: single-kernel exclusive scan (decoupled lookback) --------
// Also fuses: dis = rsqrt(deg+1), pos init, row[NN], ax seed = dis^2 * x.
// 98 blocks of 1024 threads: all co-resident on 148 SMs -> spin is safe.
__global__ void k_scan(const float* __restrict__ x) {
    __shared__ int ss[SCAN_B];
    __shared__ int s_base;
    int tid = threadIdx.x, bid = blockIdx.x;
    int i = bid * SCAN_B + tid;
    int v = (i < NN) ? g_cnt[i] : 0;
    ss[tid] = v;
    __syncthreads();
#pragma unroll
    for (int off = 1; off < SCAN_B; off <<= 1) {
        int t = (tid >= off) ? ss[tid - off] : 0;
        __syncthreads();
        ss[tid] += t;
        __syncthreads();
    }
    int incl  = ss[tid];
    int total = ss[SCAN_B - 1];
    if (tid == 0) {
        unsigned long long pub = (bid == 0)
            ? ((2ULL << 62) | (unsigned long long)(unsigned)total)
            : ((1ULL << 62) | (unsigned long long)(unsigned)total);
        atomicExch(&g_look[bid], pub);
        int base = 0;
        if (bid > 0) {
            int j = bid - 1;
            while (true) {
                unsigned long long v2;
                do { v2 = atomicOr(&g_look[j], 0ULL); } while ((v2 >> 62) == 0ULL);
                base += (int)(v2 & 0xFFFFFFFFULL);
                if ((v2 >> 62) == 2ULL) break;
                j--;
            }
            atomicExch(&g_look[bid],
                       (2ULL << 62) | (unsigned long long)(unsigned)(base + total));
        }
        s_base = base;
    }
    __syncthreads();
    int base = s_base;
    if (i < NN) {
        int r = incl - v + base;           // exclusive prefix
        g_row[i] = r;
        g_pos[i] = r;
        float dd = rsqrtf((float)(g_cnt[i] + 1));   // +1 self-loop
        g_dis[i] = dd;
        float4 xv = *reinterpret_cast<const float4*>(x + (size_t)i * 4);
        float d2 = dd * dd;
        float4 o; o.x = d2 * xv.x; o.y = d2 * xv.y; o.z = d2 * xv.z; o.w = d2 * xv.w;
        g_ax[i] = o;                       // self-loop seed of layer-1 aggregate
    }
    if (i == 0) g_row[NN] = NE;
}

// -------- 3: CSR placement + layer-1 scatter aggregation --------
__global__ void k_place(const int* __restrict__ src, const int* __restrict__ dst,
                        const float* __restrict__ x) {
    int e = blockIdx.x * blockDim.x + threadIdx.x;
    if (e >= NE) return;
    int s = src[e], d = dst[e];
    float w = g_dis[s] * g_dis[d];
    int idx = atomicAdd(&g_pos[d], 1);
    int2 ev; ev.x = s; ev.y = __float_as_int(w);
    g_e[idx] = ev;
    float4 xv = __ldg(reinterpret_cast<const float4*>(x) + s);
    float* axp = reinterpret_cast<float*>(g_ax) + (size_t)d * 4;
    atomicAdd(axp + 0, w * xv.x);
    atomicAdd(axp + 1, w * xv.y);
    atomicAdd(axp + 2, w * xv.z);
    atomicAdd(axp + 3, w * xv.w);
}

// -------- 4: fused layer-2 agg (h1 recomputed on the fly) + dense + P,Q --------
// Block: 512 thr = 16 warps = 16 nodes. Stage A: per edge, broadcast-load
// ax[s] (16B, L1-resident), h1[s] cols (2l,2l+1) = relu(ax@W1+b1) in-register,
// accumulate w*h1. Then h2 = relu(tmp@W2+b2), P/Q = h2@Wm1 halves -> fp16.
__global__ void k_agg_dense2(const float* __restrict__ W1, const float* __restrict__ b1,
                             const float* __restrict__ W2, const float* __restrict__ b2,
                             const float* __restrict__ Wm1, const float* __restrict__ bm1) {
    __shared__ float sbuf[9216];      // 4096 Wa | 4096 Wb | 1024 node tile
    float* sWa = sbuf;
    float* sWb = sbuf + 4096;
    float* sIn = sbuf + 8192;
    int tid  = threadIdx.x;
    int nb   = blockIdx.x * 16;
    int wid  = tid >> 5, lane = tid & 31;

    // stage A
    {
        int c0 = 2 * lane, c1 = c0 + 1;
        float4 wA, wB;
        wA.x = __ldg(W1 + c0);       wB.x = __ldg(W1 + c1);
        wA.y = __ldg(W1 + 64 + c0);  wB.y = __ldg(W1 + 64 + c1);
        wA.z = __ldg(W1 + 128 + c0); wB.z = __ldg(W1 + 128 + c1);
        wA.w = __ldg(W1 + 192 + c0); wB.w = __ldg(W1 + 192 + c1);
        float bA = __ldg(b1 + c0), bB = __ldg(b1 + c1);

        int node = nb + wid;
        int r = g_row[node], r1 = g_row[node + 1];
        float a0 = 0.f, a1 = 0.f;
        for (; r + 3 < r1; r += 4) {
#pragma unroll
            for (int u = 0; u < 4; u++) {
                int2 ev = g_e[r + u];
                float4 av = __ldg(&g_ax[ev.x]);          // broadcast across warp
                float we = __int_as_float(ev.y);
                float h0 = fmaxf(av.x * wA.x + av.y * wA.y + av.z * wA.z + av.w * wA.w + bA, 0.f);
                float h1 = fmaxf(av.x * wB.x + av.y * wB.y + av.z * wB.z + av.w * wB.w + bB, 0.f);
                a0 += we * h0;
                a1 += we * h1;
            }
        }
        for (; r < r1; r++) {
            int2 ev = g_e[r];
            float4 av = __ldg(&g_ax[ev.x]);
            float we = __int_as_float(ev.y);
            float h0 = fmaxf(av.x * wA.x + av.y * wA.y + av.z * wA.z + av.w * wA.w + bA, 0.f);
            float h1 = fmaxf(av.x * wB.x + av.y * wB.y + av.z * wB.z + av.w * wB.w + bB, 0.f);
            a0 += we * h0;
            a1 += we * h1;
        }
        // layer-2 self-loop: + dis^2 * h1[node]
        float dd = g_dis[node]; dd *= dd;
        float4 av = g_ax[node];
        float h0 = fmaxf(av.x * wA.x + av.y * wA.y + av.z * wA.z + av.w * wA.w + bA, 0.f);
        float h1 = fmaxf(av.x * wB.x + av.y * wB.y + av.z * wB.z + av.w * wB.w + bB, 0.f);
        a0 += dd * h0;
        a1 += dd * h1;
        sIn[wid * 64 + c0] = a0;
        sIn[wid * 64 + c1] = a1;
    }
    for (int i = tid; i < 4096; i += 512) sWa[i] = W2[i];
    __syncthreads();

    // stage B: h2 = relu(tmp@W2 + b2) in registers
    int col = tid & 63, ng = tid >> 6;    // ng 0..7, 2 nodes per thread
    float hreg[2];
    {
        float a[2] = {0.f, 0.f};
#pragma unroll 8
        for (int k = 0; k < 64; k++) {
            float wv = sWa[k * 64 + col];
            a[0] += sIn[ng * 64 + k] * wv;
            a[1] += sIn[(ng + 8) * 64 + k] * wv;
        }
        float bb = __ldg(b2 + col);
        hreg[0] = fmaxf(a[0] + bb, 0.f);
        hreg[1] = fmaxf(a[1] + bb, 0.f);
    }
    __syncthreads();

    // stage C: P,Q = h2 @ Wm1 halves -> fp16
    sIn[ng * 64 + col]       = hreg[0];
    sIn[(ng + 8) * 64 + col] = hreg[1];
    for (int i = tid; i < 4096; i += 512) { sWa[i] = Wm1[i]; sWb[i] = Wm1[4096 + i]; }
    __syncthreads();
    float p[2] = {0.f, 0.f}, q[2] = {0.f, 0.f};
#pragma unroll 8
    for (int k = 0; k < 64; k++) {
        float wa = sWa[k * 64 + col];
        float wb = sWb[k * 64 + col];
        float x0 = sIn[ng * 64 + k];
        float x1 = sIn[(ng + 8) * 64 + k];
        p[0] += x0 * wa; q[0] += x0 * wb;
        p[1] += x1 * wa; q[1] += x1 * wb;
    }
    float bmv = __ldg(bm1 + col);
#pragma unroll
    for (int m = 0; m < 2; m++) {
        size_t o = (size_t)(nb + ng + 8 * m) * 64 + col;
        g_Ph[o] = __float2half(p[m] + bmv);
        g_Qh[o] = __float2half(q[m]);
    }
}

// -------- 5: edge epilogue: out[e] = relu(P[s]+Q[d]+ea@Wea) @ Wm2 + bm2 --------
__global__ void k_edge(const int* __restrict__ src, const int* __restrict__ dst,
                       const float* __restrict__ ea,
                       const float* __restrict__ Wm1,
                       const float* __restrict__ Wm2, const float* __restrict__ bm2,
                       float* __restrict__ out) {
    int l  = threadIdx.x & 15;
    int c0 = l * 4;
    float4 w0 = *reinterpret_cast<const float4*>(Wm1 + 128 * 64 + c0);
    float4 w1 = *reinterpret_cast<const float4*>(Wm1 + 129 * 64 + c0);
    float4 w2 = *reinterpret_cast<const float4*>(Wm1 + 130 * 64 + c0);
    float4 w3 = *reinterpret_cast<const float4*>(Wm1 + 131 * 64 + c0);
    float4 wo = *reinterpret_cast<const float4*>(Wm2 + c0);
    float  ob = bm2[0];

    int grp  = (blockIdx.x * blockDim.x + threadIdx.x) >> 4;
    int ngrp = (gridDim.x * blockDim.x) >> 4;
    for (int e0 = grp; e0 < NE; e0 += 4 * ngrp) {
        float part[4];
        int   ee[4];
        bool  ok[4];
#pragma unroll
        for (int u = 0; u < 4; u++) {
            int e = e0 + u * ngrp;
            ok[u] = (e < NE);
            ee[u] = ok[u] ? e : e0;
            int s = src[ee[u]], d = dst[ee[u]];
            uint2 pv = *reinterpret_cast<const uint2*>(g_Ph + (size_t)s * 64 + c0);
            uint2 qv = *reinterpret_cast<const uint2*>(g_Qh + (size_t)d * 64 + c0);
            float4 a = *reinterpret_cast<const float4*>(ea + (size_t)ee[u] * 4);
            float2 p01 = __half22float2(*reinterpret_cast<__half2*>(&pv.x));
            float2 p23 = __half22float2(*reinterpret_cast<__half2*>(&pv.y));
            float2 q01 = __half22float2(*reinterpret_cast<__half2*>(&qv.x));
            float2 q23 = __half22float2(*reinterpret_cast<__half2*>(&qv.y));
            float z0 = p01.x + q01.x + a.x * w0.x + a.y * w1.x + a.z * w2.x + a.w * w3.x;
            float z1 = p01.y + q01.y + a.x * w0.y + a.y * w1.y + a.z * w2.y + a.w * w3.y;
            float z2 = p23.x + q23.x + a.x * w0.z + a.y * w1.z + a.z * w2.z + a.w * w3.z;
            float z3 = p23.y + q23.y + a.x * w0.w + a.y * w1.w + a.z * w2.w + a.w * w3.w;
            z0 = fmaxf(z0, 0.f); z1 = fmaxf(z1, 0.f); z2 = fmaxf(z2, 0.f); z3 = fmaxf(z3, 0.f);
            part[u] = z0 * wo.x + z1 * wo.y + z2 * wo.z + z3 * wo.w;
        }
#pragma unroll
        for (int off = 8; off >= 1; off >>= 1) {
#pragma unroll
            for (int u = 0; u < 4; u++)
                part[u] += __shfl_down_sync(0xffffffffu, part[u], off, 16);
        }
        if (l == 0) {
#pragma unroll
            for (int u = 0; u < 4; u++)
                if (ok[u]) out[ee[u]] = part[u] + ob;
        }
    }
}

extern "C" void kernel_launch(void* const* d_in, const int* in_sizes, int n_in,
                              void* d_out, int out_size) {
    const float* x   = (const float*)d_in[0];
    const int*   ei  = (const int*)  d_in[1];   // [2, NE] int32
    const float* ea  = (const float*)d_in[2];
    const float* W1  = (const float*)d_in[3];
    const float* b1  = (const float*)d_in[4];
    const float* W2  = (const float*)d_in[5];
    const float* b2  = (const float*)d_in[6];
    const float* Wm1 = (const float*)d_in[7];
    const float* bm1 = (const float*)d_in[8];
    const float* Wm2 = (const float*)d_in[9];
    const float* bm2 = (const float*)d_in[10];
    float* out = (float*)d_out;

    const int* src = ei;
    const int* dst = ei + NE;

    // zero counters via memset nodes (not kernel launches)
    void* p_cnt  = nullptr;
    void* p_look = nullptr;
    cudaGetSymbolAddress(&p_cnt,  g_cnt);
    cudaGetSymbolAddress(&p_look, g_look);
    cudaMemsetAsync(p_cnt,  0, NN * sizeof(int), 0);
    cudaMemsetAsync(p_look, 0, NB * sizeof(unsigned long long), 0);

    const int TB = 256;
    int ne_blk = (NE + TB - 1) / TB;

    k_hist <<<ne_blk, TB>>>(dst);                       // kernel 1
    k_scan <<<NB, SCAN_B>>>(x);                         // kernel 2
    k_place<<<ne_blk, TB>>>(src, dst, x);               // kernel 3
    k_agg_dense2<<<NN / 16, 512>>>(W1, b1, W2, b2, Wm1, bm1);  // kernel 4 (capture slot)
    k_edge <<<1184, TB>>>(src, dst, ea, Wm1, Wm2, bm2, out);   // kernel 5
}

// round 11
// speedup vs baseline: 1.0702x; 1.0702x over previous
#include <cuda_runtime.h>
#include <cuda_fp16.h>

#define NN 100000
#define NE 3200000
#define H  64
#define SCAN_B 1024
#define NB 98                      // ceil(NN / SCAN_B)
#define PAD 68                     // 64 + 4: 16B-aligned, conflict-free LDS.128

// -------- device scratch (no allocations allowed) --------
__device__ int    g_cnt[NN];
__device__ int    g_row[NN + 1];
__device__ int    g_pos[NN];
__device__ float  g_dis[NN];
__device__ unsigned long long g_look[NB];   // lookback: status(2b)<<62 | value
__device__ int2   g_e[NE];          // CSR slot: (src, bitcast weight)
__device__ float4 g_ax[NN];         // aggregated layer-1 input (4-dim, fp32)
__device__ __half g_Ph[NN * H];     // fp16: h2 @ Wm1[0:64] + bm1
__device__ __half g_Qh[NN * H];     // fp16: h2 @ Wm1[64:128]

// -------- 1: histogram of in-degrees --------
__global__ void k_hist(const int* __restrict__ dst) {
    int e = blockIdx.x * blockDim.x + threadIdx.x;
    if (e < NE) atomicAdd(&g_cnt[dst[e]], 1);
}

// -------- 2: single-kernel exclusive scan (decoupled lookback) --------
// Fuses: dis = rsqrt(deg+1), pos init, row[NN], ax seed = dis^2 * x.
__global__ void k_scan(const float* __restrict__ x) {
    __shared__ int ss[SCAN_B];
    __shared__ int s_base;
    int tid = threadIdx.x, bid = blockIdx.x;
    int i = bid * SCAN_B + tid;
    int v = (i < NN) ? g_cnt[i] : 0;
    ss[tid] = v;
    __syncthreads();
#pragma unroll
    for (int off = 1; off < SCAN_B; off <<= 1) {
        int t = (tid >= off) ? ss[tid - off] : 0;
        __syncthreads();
        ss[tid] += t;
        __syncthreads();
    }
    int incl  = ss[tid];
    int total = ss[SCAN_B - 1];
    if (tid == 0) {
        unsigned long long pub = (bid == 0)
            ? ((2ULL << 62) | (unsigned long long)(unsigned)total)
            : ((1ULL << 62) | (unsigned long long)(unsigned)total);
        atomicExch(&g_look[bid], pub);
        int base = 0;
        if (bid > 0) {
            int j = bid - 1;
            while (true) {
                unsigned long long v2;
                do { v2 = atomicOr(&g_look[j], 0ULL); } while ((v2 >> 62) == 0ULL);
                base += (int)(v2 & 0xFFFFFFFFULL);
                if ((v2 >> 62) == 2ULL) break;
                j--;
            }
            atomicExch(&g_look[bid],
                       (2ULL << 62) | (unsigned long long)(unsigned)(base + total));
        }
        s_base = base;
    }
    __syncthreads();
    int base = s_base;
    if (i < NN) {
        int r = incl - v + base;           // exclusive prefix
        g_row[i] = r;
        g_pos[i] = r;
        float dd = rsqrtf((float)(g_cnt[i] + 1));   // +1 self-loop
        g_dis[i] = dd;
        float4 xv = *reinterpret_cast<const float4*>(x + (size_t)i * 4);
        float d2 = dd * dd;
        float4 o; o.x = d2 * xv.x; o.y = d2 * xv.y; o.z = d2 * xv.z; o.w = d2 * xv.w;
        g_ax[i] = o;                       // self-loop seed of layer-1 aggregate
    }
    if (i == 0) g_row[NN] = NE;
}

// -------- 3: CSR placement + layer-1 scatter aggregation --------
__global__ void k_place(const int* __restrict__ src, const int* __restrict__ dst,
                        const float* __restrict__ x) {
    int e = blockIdx.x * blockDim.x + threadIdx.x;
    if (e >= NE) return;
    int s = src[e], d = dst[e];
    float w = g_dis[s] * g_dis[d];
    int idx = atomicAdd(&g_pos[d], 1);
    int2 ev; ev.x = s; ev.y = __float_as_int(w);
    g_e[idx] = ev;
    float4 xv = __ldg(reinterpret_cast<const float4*>(x) + s);
    float* axp = reinterpret_cast<float*>(g_ax) + (size_t)d * 4;
    atomicAdd(axp + 0, w * xv.x);
    atomicAdd(axp + 1, w * xv.y);
    atomicAdd(axp + 2, w * xv.z);
    atomicAdd(axp + 3, w * xv.w);
}

// -------- 4: fused layer-2 agg + dense + P,Q (register-tiled GEMM stages) ----
// Block: 512 thr = 16 warps = 16 nodes.
// Stage A: warp per node; per edge, broadcast ax[s], h1 cols (2l,2l+1) in-reg,
//          8-deep unroll for L2 MLP.
// Stage B/C: transposed-weight smem tiles (PAD=68), LDS.128 register tiling.
__global__ void k_agg_dense2(const float* __restrict__ W1, const float* __restrict__ b1,
                             const float* __restrict__ W2, const float* __restrict__ b2,
                             const float* __restrict__ Wm1, const float* __restrict__ bm1) {
    __shared__ float sWa[64 * PAD];          // transposed weight tile A [col][k]
    __shared__ float sWb[64 * PAD];          // transposed weight tile B [col][k]
    __shared__ float sIn[16 * PAD];          // node tile [node][k]
    int tid  = threadIdx.x;
    int nb   = blockIdx.x * 16;
    int wid  = tid >> 5, lane = tid & 31;

    // ---- stage A: aggregate w*h1 over in-edges, h1 recomputed from ax ----
    {
        int c0 = 2 * lane, c1 = c0 + 1;
        float4 wA, wB;
        wA.x = __ldg(W1 + c0);       wB.x = __ldg(W1 + c1);
        wA.y = __ldg(W1 + 64 + c0);  wB.y = __ldg(W1 + 64 + c1);
        wA.z = __ldg(W1 + 128 + c0); wB.z = __ldg(W1 + 128 + c1);
        wA.w = __ldg(W1 + 192 + c0); wB.w = __ldg(W1 + 192 + c1);
        float bA = __ldg(b1 + c0), bB = __ldg(b1 + c1);

        int node = nb + wid;
        int r = g_row[node], r1 = g_row[node + 1];
        float a0 = 0.f, a1 = 0.f;
        for (; r + 7 < r1; r += 8) {
            int2 ev[8];
#pragma unroll
            for (int u = 0; u < 8; u++) ev[u] = g_e[r + u];
            float4 av[8];
#pragma unroll
            for (int u = 0; u < 8; u++) av[u] = __ldg(&g_ax[ev[u].x]);
#pragma unroll
            for (int u = 0; u < 8; u++) {
                float we = __int_as_float(ev[u].y);
                float h0 = fmaxf(av[u].x * wA.x + av[u].y * wA.y + av[u].z * wA.z + av[u].w * wA.w + bA, 0.f);
                float h1 = fmaxf(av[u].x * wB.x + av[u].y * wB.y + av[u].z * wB.z + av[u].w * wB.w + bB, 0.f);
                a0 += we * h0;
                a1 += we * h1;
            }
        }
        for (; r < r1; r++) {
            int2 ev = g_e[r];
            float4 av = __ldg(&g_ax[ev.x]);
            float we = __int_as_float(ev.y);
            float h0 = fmaxf(av.x * wA.x + av.y * wA.y + av.z * wA.z + av.w * wA.w + bA, 0.f);
            float h1 = fmaxf(av.x * wB.x + av.y * wB.y + av.z * wB.z + av.w * wB.w + bB, 0.f);
            a0 += we * h0;
            a1 += we * h1;
        }
        // layer-2 self-loop: + dis^2 * h1[node]
        float dd = g_dis[node]; dd *= dd;
        float4 av = g_ax[node];
        float h0 = fmaxf(av.x * wA.x + av.y * wA.y + av.z * wA.z + av.w * wA.w + bA, 0.f);
        float h1 = fmaxf(av.x * wB.x + av.y * wB.y + av.z * wB.z + av.w * wB.w + bB, 0.f);
        a0 += dd * h0;
        a1 += dd * h1;
        sIn[wid * PAD + c0] = a0;
        sIn[wid * PAD + c1] = a1;
    }
    // W2 transposed into sWa: sWa[col][k] = W2[k][col]
    for (int i = tid; i < 4096; i += 512)
        sWa[(i & 63) * PAD + (i >> 6)] = W2[i];
    __syncthreads();

    // ---- stage B: h2 = relu(tmp @ W2 + b2), register-tiled ----
    int col = tid & 63, ng = tid >> 6;    // ng 0..7, nodes ng and ng+8
    float hreg[2];
    {
        const float4* wp = reinterpret_cast<const float4*>(sWa + col * PAD);
        const float4* i0 = reinterpret_cast<const float4*>(sIn + ng * PAD);
        const float4* i1 = reinterpret_cast<const float4*>(sIn + (ng + 8) * PAD);
        float a0 = 0.f, a1 = 0.f;
#pragma unroll
        for (int k4 = 0; k4 < 16; k4++) {
            float4 w = wp[k4];
            float4 v0 = i0[k4];
            float4 v1 = i1[k4];
            a0 += v0.x * w.x + v0.y * w.y + v0.z * w.z + v0.w * w.w;
            a1 += v1.x * w.x + v1.y * w.y + v1.z * w.z + v1.w * w.w;
        }
        float bb = __ldg(b2 + col);
        hreg[0] = fmaxf(a0 + bb, 0.f);
        hreg[1] = fmaxf(a1 + bb, 0.f);
    }
    __syncthreads();

    // ---- stage C: P,Q = h2 @ Wm1 halves, register-tiled ----
    sIn[ng * PAD + col]       = hreg[0];
    sIn[(ng + 8) * PAD + col] = hreg[1];
    for (int i = tid; i < 4096; i += 512) {
        int k = i >> 6, c = i & 63;
        sWa[c * PAD + k] = Wm1[i];
        sWb[c * PAD + k] = Wm1[4096 + i];
    }
    __syncthreads();
    {
        const float4* wa = reinterpret_cast<const float4*>(sWa + col * PAD);
        const float4* wb = reinterpret_cast<const float4*>(sWb + col * PAD);
        const float4* i0 = reinterpret_cast<const float4*>(sIn + ng * PAD);
        const float4* i1 = reinterpret_cast<const float4*>(sIn + (ng + 8) * PAD);
        float p0 = 0.f, p1 = 0.f, q0 = 0.f, q1 = 0.f;
#pragma unroll
        for (int k4 = 0; k4 < 16; k4++) {
            float4 a = wa[k4];
            float4 b = wb[k4];
            float4 v0 = i0[k4];
            float4 v1 = i1[k4];
            p0 += v0.x * a.x + v0.y * a.y + v0.z * a.z + v0.w * a.w;
            q0 += v0.x * b.x + v0.y * b.y + v0.z * b.z + v0.w * b.w;
            p1 += v1.x * a.x + v1.y * a.y + v1.z * a.z + v1.w * a.w;
            q1 += v1.x * b.x + v1.y * b.y + v1.z * b.z + v1.w * b.w;
        }
        float bmv = __ldg(bm1 + col);
        size_t o0 = (size_t)(nb + ng) * 64 + col;
        size_t o1 = (size_t)(nb + ng + 8) * 64 + col;
        g_Ph[o0] = __float2half(p0 + bmv);
        g_Qh[o0] = __float2half(q0);
        g_Ph[o1] = __float2half(p1 + bmv);
        g_Qh[o1] = __float2half(q1);
    }
}

// -------- 5: edge epilogue: out[e] = relu(P[s]+Q[d]+ea@Wea) @ Wm2 + bm2 -----
__global__ void k_edge(const int* __restrict__ src, const int* __restrict__ dst,
                       const float* __restrict__ ea,
                       const float* __restrict__ Wm1,
                       const float* __restrict__ Wm2, const float* __restrict__ bm2,
                       float* __restrict__ out) {
    int l  = threadIdx.x & 15;
    int c0 = l * 4;
    float4 w0 = *reinterpret_cast<const float4*>(Wm1 + 128 * 64 + c0);
    float4 w1 = *reinterpret_cast<const float4*>(Wm1 + 129 * 64 + c0);
    float4 w2 = *reinterpret_cast<const float4*>(Wm1 + 130 * 64 + c0);
    float4 w3 = *reinterpret_cast<const float4*>(Wm1 + 131 * 64 + c0);
    float4 wo = *reinterpret_cast<const float4*>(Wm2 + c0);
    float  ob = bm2[0];

    int grp  = (blockIdx.x * blockDim.x + threadIdx.x) >> 4;
    int ngrp = (gridDim.x * blockDim.x) >> 4;
    for (int e0 = grp; e0 < NE; e0 += 4 * ngrp) {
        float part[4];
        int   ee[4];
        bool  ok[4];
#pragma unroll
        for (int u = 0; u < 4; u++) {
            int e = e0 + u * ngrp;
            ok[u] = (e < NE);
            ee[u] = ok[u] ? e : e0;
            int s = src[ee[u]], d = dst[ee[u]];
            uint2 pv = *reinterpret_cast<const uint2*>(g_Ph + (size_t)s * 64 + c0);
            uint2 qv = *reinterpret_cast<const uint2*>(g_Qh + (size_t)d * 64 + c0);
            float4 a = *reinterpret_cast<const float4*>(ea + (size_t)ee[u] * 4);
            float2 p01 = __half22float2(*reinterpret_cast<__half2*>(&pv.x));
            float2 p23 = __half22float2(*reinterpret_cast<__half2*>(&pv.y));
            float2 q01 = __half22float2(*reinterpret_cast<__half2*>(&qv.x));
            float2 q23 = __half22float2(*reinterpret_cast<__half2*>(&qv.y));
            float z0 = p01.x + q01.x + a.x * w0.x + a.y * w1.x + a.z * w2.x + a.w * w3.x;
            float z1 = p01.y + q01.y + a.x * w0.y + a.y * w1.y + a.z * w2.y + a.w * w3.y;
            float z2 = p23.x + q23.x + a.x * w0.z + a.y * w1.z + a.z * w2.z + a.w * w3.z;
            float z3 = p23.y + q23.y + a.x * w0.w + a.y * w1.w + a.z * w2.w + a.w * w3.w;
            z0 = fmaxf(z0, 0.f); z1 = fmaxf(z1, 0.f); z2 = fmaxf(z2, 0.f); z3 = fmaxf(z3, 0.f);
            part[u] = z0 * wo.x + z1 * wo.y + z2 * wo.z + z3 * wo.w;
        }
#pragma unroll
        for (int off = 8; off >= 1; off >>= 1) {
#pragma unroll
            for (int u = 0; u < 4; u++)
                part[u] += __shfl_down_sync(0xffffffffu, part[u], off, 16);
        }
        if (l == 0) {
#pragma unroll
            for (int u = 0; u < 4; u++)
                if (ok[u]) out[ee[u]] = part[u] + ob;
        }
    }
}

extern "C" void kernel_launch(void* const* d_in, const int* in_sizes, int n_in,
                              void* d_out, int out_size) {
    const float* x   = (const float*)d_in[0];
    const int*   ei  = (const int*)  d_in[1];   // [2, NE] int32
    const float* ea  = (const float*)d_in[2];
    const float* W1  = (const float*)d_in[3];
    const float* b1  = (const float*)d_in[4];
    const float* W2  = (const float*)d_in[5];
    const float* b2  = (const float*)d_in[6];
    const float* Wm1 = (const float*)d_in[7];
    const float* bm1 = (const float*)d_in[8];
    const float* Wm2 = (const float*)d_in[9];
    const float* bm2 = (const float*)d_in[10];
    float* out = (float*)d_out;

    const int* src = ei;
    const int* dst = ei + NE;

    // zero counters via memset nodes (not kernel launches)
    void* p_cnt  = nullptr;
    void* p_look = nullptr;
    cudaGetSymbolAddress(&p_cnt,  g_cnt);
    cudaGetSymbolAddress(&p_look, g_look);
    cudaMemsetAsync(p_cnt,  0, NN * sizeof(int), 0);
    cudaMemsetAsync(p_look, 0, NB * sizeof(unsigned long long), 0);

    const int TB = 256;
    int ne_blk = (NE + TB - 1) / TB;

    k_hist <<<ne_blk, TB>>>(dst);                       // kernel 1
    k_scan <<<NB, SCAN_B>>>(x);                         // kernel 2
    k_place<<<ne_blk, TB>>>(src, dst, x);               // kernel 3
    k_agg_dense2<<<NN / 16, 512>>>(W1, b1, W2, b2, Wm1, bm1);  // kernel 4 (capture slot)
    k_edge <<<1184, TB>>>(src, dst, ea, Wm1, Wm2, bm2, out);   // kernel 5
}

// round 13
// speedup vs baseline: 1.2446x; 1.1630x over previous
#include <cuda_runtime.h>
#include <cuda_fp16.h>

#define NN 100000
#define NE 3200000
#define H  64
#define SCAN_B 1024
#define NB 98                      // ceil(NN / SCAN_B)
#define PAD 68                     // 64 + 4: 16B-aligned, conflict-free LDS.128

// -------- device scratch (no allocations allowed) --------
__device__ int     g_cnt[NN];
__device__ int     g_row[NN + 1];
__device__ int     g_pos[NN];
__device__ float   g_dis[NN];
__device__ unsigned long long g_look[NB];   // lookback: status(2b)<<62 | value
__device__ int2    g_e[NE];          // CSR slot: (src, bitcast weight)
__device__ __half2 g_h1h[NN * 32];   // h1 fp16 pairs (cols 2l, 2l+1)
__device__ __half  g_Ph[NN * H];     // fp16: h2 @ Wm1[0:64] + bm1
__device__ __half  g_Qh[NN * H];     // fp16: h2 @ Wm1[64:128]

// -------- 1: histogram of in-degrees --------
__global__ void k_hist(const int* __restrict__ dst) {
    int e = blockIdx.x * blockDim.x + threadIdx.x;
    if (e < NE) atomicAdd(&g_cnt[dst[e]], 1);
}

// -------- 2: single-kernel exclusive scan (decoupled lookback) --------
// Fuses: dis = rsqrt(deg+1), pos init, row[NN].
__global__ void k_scan() {
    __shared__ int ss[SCAN_B];
    __shared__ int s_base;
    int tid = threadIdx.x, bid = blockIdx.x;
    int i = bid * SCAN_B + tid;
    int v = (i < NN) ? g_cnt[i] : 0;
    ss[tid] = v;
    __syncthreads();
#pragma unroll
    for (int off = 1; off < SCAN_B; off <<= 1) {
        int t = (tid >= off) ? ss[tid - off] : 0;
        __syncthreads();
        ss[tid] += t;
        __syncthreads();
    }
    int incl  = ss[tid];
    int total = ss[SCAN_B - 1];
    if (tid == 0) {
        unsigned long long pub = (bid == 0)
            ? ((2ULL << 62) | (unsigned long long)(unsigned)total)
            : ((1ULL << 62) | (unsigned long long)(unsigned)total);
        atomicExch(&g_look[bid], pub);
        int base = 0;
        if (bid > 0) {
            int j = bid - 1;
            while (true) {
                unsigned long long v2;
                do { v2 = atomicOr(&g_look[j], 0ULL); } while ((v2 >> 62) == 0ULL);
                base += (int)(v2 & 0xFFFFFFFFULL);
                if ((v2 >> 62) == 2ULL) break;
                j--;
            }
            atomicExch(&g_look[bid],
                       (2ULL << 62) | (unsigned long long)(unsigned)(base + total));
        }
        s_base = base;
    }
    __syncthreads();
    int base = s_base;
    if (i < NN) {
        int r = incl - v + base;           // exclusive prefix
        g_row[i] = r;
        g_pos[i] = r;
        g_dis[i] = rsqrtf((float)(g_cnt[i] + 1));   // +1 self-loop
    }
    if (i == 0) g_row[NN] = NE;
}

// -------- 3: CSR placement --------
__global__ void k_place(const int* __restrict__ src, const int* __restrict__ dst) {
    int e = blockIdx.x * blockDim.x + threadIdx.x;
    if (e >= NE) return;
    int s = src[e], d = dst[e];
    int idx = atomicAdd(&g_pos[d], 1);
    int2 ev; ev.x = s; ev.y = __float_as_int(g_dis[s] * g_dis[d]);
    g_e[idx] = ev;
}

// -------- 4: fused layer 1: warp per node; h1 out in fp16 pairs --------
__global__ void k_aggx_h1(const float* __restrict__ x,
                          const float* __restrict__ W1, const float* __restrict__ b1) {
    int w = (blockIdx.x * blockDim.x + threadIdx.x) >> 5;
    if (w >= NN) return;
    int lane = threadIdx.x & 31;
    int r0 = g_row[w], r1 = g_row[w + 1];
    float ax = 0.f, ay = 0.f, az = 0.f, aw = 0.f;
#pragma unroll 4
    for (int r = r0 + lane; r < r1; r += 32) {
        int2 ev = g_e[r];
        float ww = __int_as_float(ev.y);
        float4 xv = *reinterpret_cast<const float4*>(x + (size_t)ev.x * 4);
        ax += xv.x * ww; ay += xv.y * ww; az += xv.z * ww; aw += xv.w * ww;
    }
    if (lane == 0) {                     // self-loop
        float dd = g_dis[w]; dd *= dd;
        float4 xv = *reinterpret_cast<const float4*>(x + (size_t)w * 4);
        ax += dd * xv.x; ay += dd * xv.y; az += dd * xv.z; aw += dd * xv.w;
    }
#pragma unroll
    for (int off = 16; off >= 1; off >>= 1) {
        ax += __shfl_xor_sync(0xffffffffu, ax, off);
        ay += __shfl_xor_sync(0xffffffffu, ay, off);
        az += __shfl_xor_sync(0xffffffffu, az, off);
        aw += __shfl_xor_sync(0xffffffffu, aw, off);
    }
    int c0 = 2 * lane, c1 = c0 + 1;
    float s0 = ax * __ldg(W1 + c0) + ay * __ldg(W1 + 64 + c0)
             + az * __ldg(W1 + 128 + c0) + aw * __ldg(W1 + 192 + c0) + __ldg(b1 + c0);
    float s1 = ax * __ldg(W1 + c1) + ay * __ldg(W1 + 64 + c1)
             + az * __ldg(W1 + 128 + c1) + aw * __ldg(W1 + 192 + c1) + __ldg(b1 + c1);
    g_h1h[(size_t)w * 32 + lane] = __floats2half2_rn(fmaxf(s0, 0.f), fmaxf(s1, 0.f));
}

// -------- 5: fused layer-2 agg (fp16 h1 gather) + tiled dense + P,Q --------
// Block: 512 thr = 16 warps = 16 nodes.
__global__ void k_agg_dense2(const float* __restrict__ W2, const float* __restrict__ b2,
                             const float* __restrict__ Wm1, const float* __restrict__ bm1) {
    __shared__ float sWa[64 * PAD];          // transposed weight tile A [col][k]
    __shared__ float sWb[64 * PAD];          // transposed weight tile B [col][k]
    __shared__ float sIn[16 * PAD];          // node tile [node][k]
    int tid  = threadIdx.x;
    int nb   = blockIdx.x * 16;
    int wid  = tid >> 5, lane = tid & 31;

    // ---- stage A: gather fp16 h1 rows, 8-deep unroll ----
    {
        int node = nb + wid;
        int r = g_row[node], r1 = g_row[node + 1];
        float a0 = 0.f, a1 = 0.f;
        for (; r + 7 < r1; r += 8) {
            int2 ev[8];
#pragma unroll
            for (int u = 0; u < 8; u++) ev[u] = g_e[r + u];
            __half2 hv[8];
#pragma unroll
            for (int u = 0; u < 8; u++) hv[u] = g_h1h[(size_t)ev[u].x * 32 + lane];
#pragma unroll
            for (int u = 0; u < 8; u++) {
                float2 v = __half22float2(hv[u]);
                float we = __int_as_float(ev[u].y);
                a0 += v.x * we;
                a1 += v.y * we;
            }
        }
        for (; r < r1; r++) {
            int2 ev = g_e[r];
            float2 v = __half22float2(g_h1h[(size_t)ev.x * 32 + lane]);
            float we = __int_as_float(ev.y);
            a0 += v.x * we;
            a1 += v.y * we;
        }
        float dd = g_dis[node]; dd *= dd;     // self-loop
        float2 v = __half22float2(g_h1h[(size_t)node * 32 + lane]);
        a0 += v.x * dd;
        a1 += v.y * dd;
        sIn[wid * PAD + 2 * lane]     = a0;
        sIn[wid * PAD + 2 * lane + 1] = a1;
    }
    // W2 transposed into sWa: sWa[col][k] = W2[k][col]
    for (int i = tid; i < 4096; i += 512)
        sWa[(i & 63) * PAD + (i >> 6)] = W2[i];
    __syncthreads();

    // ---- stage B: h2 = relu(tmp @ W2 + b2), register-tiled ----
    int col = tid & 63, ng = tid >> 6;    // ng 0..7, nodes ng and ng+8
    float hreg[2];
    {
        const float4* wp = reinterpret_cast<const float4*>(sWa + col * PAD);
        const float4* i0 = reinterpret_cast<const float4*>(sIn + ng * PAD);
        const float4* i1 = reinterpret_cast<const float4*>(sIn + (ng + 8) * PAD);
        float a0 = 0.f, a1 = 0.f;
#pragma unroll
        for (int k4 = 0; k4 < 16; k4++) {
            float4 w = wp[k4];
            float4 v0 = i0[k4];
            float4 v1 = i1[k4];
            a0 += v0.x * w.x + v0.y * w.y + v0.z * w.z + v0.w * w.w;
            a1 += v1.x * w.x + v1.y * w.y + v1.z * w.z + v1.w * w.w;
        }
        float bb = __ldg(b2 + col);
        hreg[0] = fmaxf(a0 + bb, 0.f);
        hreg[1] = fmaxf(a1 + bb, 0.f);
    }
    __syncthreads();

    // ---- stage C: P,Q = h2 @ Wm1 halves, register-tiled ----
    sIn[ng * PAD + col]       = hreg[0];
    sIn[(ng + 8) * PAD + col] = hreg[1];
    for (int i = tid; i < 4096; i += 512) {
        int k = i >> 6, c = i & 63;
        sWa[c * PAD + k] = Wm1[i];
        sWb[c * PAD + k] = Wm1[4096 + i];
    }
    __syncthreads();
    {
        const float4* wa = reinterpret_cast<const float4*>(sWa + col * PAD);
        const float4* wb = reinterpret_cast<const float4*>(sWb + col * PAD);
        const float4* i0 = reinterpret_cast<const float4*>(sIn + ng * PAD);
        const float4* i1 = reinterpret_cast<const float4*>(sIn + (ng + 8) * PAD);
        float p0 = 0.f, p1 = 0.f, q0 = 0.f, q1 = 0.f;
#pragma unroll
        for (int k4 = 0; k4 < 16; k4++) {
            float4 a = wa[k4];
            float4 b = wb[k4];
            float4 v0 = i0[k4];
            float4 v1 = i1[k4];
            p0 += v0.x * a.x + v0.y * a.y + v0.z * a.z + v0.w * a.w;
            q0 += v0.x * b.x + v0.y * b.y + v0.z * b.z + v0.w * b.w;
            p1 += v1.x * a.x + v1.y * a.y + v1.z * a.z + v1.w * a.w;
            q1 += v1.x * b.x + v1.y * b.y + v1.z * b.z + v1.w * b.w;
        }
        float bmv = __ldg(bm1 + col);
        size_t o0 = (size_t)(nb + ng) * 64 + col;
        size_t o1 = (size_t)(nb + ng + 8) * 64 + col;
        g_Ph[o0] = __float2half(p0 + bmv);
        g_Qh[o0] = __float2half(q0);
        g_Ph[o1] = __float2half(p1 + bmv);
        g_Qh[o1] = __float2half(q1);
    }
}

// -------- 6: edge epilogue: out[e] = relu(P[s]+Q[d]+ea@Wea) @ Wm2 + bm2 -----
__global__ void k_edge(const int* __restrict__ src, const int* __restrict__ dst,
                       const float* __restrict__ ea,
                       const float* __restrict__ Wm1,
                       const float* __restrict__ Wm2, const float* __restrict__ bm2,
                       float* __restrict__ out) {
    int l  = threadIdx.x & 15;
    int c0 = l * 4;
    float4 w0 = *reinterpret_cast<const float4*>(Wm1 + 128 * 64 + c0);
    float4 w1 = *reinterpret_cast<const float4*>(Wm1 + 129 * 64 + c0);
    float4 w2 = *reinterpret_cast<const float4*>(Wm1 + 130 * 64 + c0);
    float4 w3 = *reinterpret_cast<const float4*>(Wm1 + 131 * 64 + c0);
    float4 wo = *reinterpret_cast<const float4*>(Wm2 + c0);
    float  ob = bm2[0];

    int grp  = (blockIdx.x * blockDim.x + threadIdx.x) >> 4;
    int ngrp = (gridDim.x * blockDim.x) >> 4;
    for (int e0 = grp; e0 < NE; e0 += 4 * ngrp) {
        float part[4];
        int   ee[4];
        bool  ok[4];
#pragma unroll
        for (int u = 0; u < 4; u++) {
            int e = e0 + u * ngrp;
            ok[u] = (e < NE);
            ee[u] = ok[u] ? e : e0;
            int s = src[ee[u]], d = dst[ee[u]];
            uint2 pv = *reinterpret_cast<const uint2*>(g_Ph + (size_t)s * 64 + c0);
            uint2 qv = *reinterpret_cast<const uint2*>(g_Qh + (size_t)d * 64 + c0);
            float4 a = *reinterpret_cast<const float4*>(ea + (size_t)ee[u] * 4);
            float2 p01 = __half22float2(*reinterpret_cast<__half2*>(&pv.x));
            float2 p23 = __half22float2(*reinterpret_cast<__half2*>(&pv.y));
            float2 q01 = __half22float2(*reinterpret_cast<__half2*>(&qv.x));
            float2 q23 = __half22float2(*reinterpret_cast<__half2*>(&qv.y));
            float z0 = p01.x + q01.x + a.x * w0.x + a.y * w1.x + a.z * w2.x + a.w * w3.x;
            float z1 = p01.y + q01.y + a.x * w0.y + a.y * w1.y + a.z * w2.y + a.w * w3.y;
            float z2 = p23.x + q23.x + a.x * w0.z + a.y * w1.z + a.z * w2.z + a.w * w3.z;
            float z3 = p23.y + q23.y + a.x * w0.w + a.y * w1.w + a.z * w2.w + a.w * w3.w;
            z0 = fmaxf(z0, 0.f); z1 = fmaxf(z1, 0.f); z2 = fmaxf(z2, 0.f); z3 = fmaxf(z3, 0.f);
            part[u] = z0 * wo.x + z1 * wo.y + z2 * wo.z + z3 * wo.w;
        }
#pragma unroll
        for (int off = 8; off >= 1; off >>= 1) {
#pragma unroll
            for (int u = 0; u < 4; u++)
                part[u] += __shfl_down_sync(0xffffffffu, part[u], off, 16);
        }
        if (l == 0) {
#pragma unroll
            for (int u = 0; u < 4; u++)
                if (ok[u]) out[ee[u]] = part[u] + ob;
        }
    }
}

extern "C" void kernel_launch(void* const* d_in, const int* in_sizes, int n_in,
                              void* d_out, int out_size) {
    const float* x   = (const float*)d_in[0];
    const int*   ei  = (const int*)  d_in[1];   // [2, NE] int32
    const float* ea  = (const float*)d_in[2];
    const float* W1  = (const float*)d_in[3];
    const float* b1  = (const float*)d_in[4];
    const float* W2  = (const float*)d_in[5];
    const float* b2  = (const float*)d_in[6];
    const float* Wm1 = (const float*)d_in[7];
    const float* bm1 = (const float*)d_in[8];
    const float* Wm2 = (const float*)d_in[9];
    const float* bm2 = (const float*)d_in[10];
    float* out = (float*)d_out;

    const int* src = ei;
    const int* dst = ei + NE;

    // zero counters via memset nodes (not kernel launches)
    void* p_cnt  = nullptr;
    void* p_look = nullptr;
    cudaGetSymbolAddress(&p_cnt,  g_cnt);
    cudaGetSymbolAddress(&p_look, g_look);
    cudaMemsetAsync(p_cnt,  0, NN * sizeof(int), 0);
    cudaMemsetAsync(p_look, 0, NB * sizeof(unsigned long long), 0);

    const int TB = 256;
    int ne_blk  = (NE + TB - 1) / TB;
    int agg_blk = (NN + 7) / 8;                  // 8 warps (nodes) per block

    k_hist <<<ne_blk, TB>>>(dst);                        // kernel 1
    k_scan <<<NB, SCAN_B>>>();                           // kernel 2
    k_place<<<ne_blk, TB>>>(src, dst);                   // kernel 3
    k_aggx_h1<<<agg_blk, TB>>>(x, W1, b1);               // kernel 4 (capture slot)
    k_agg_dense2<<<NN / 16, 512>>>(W2, b2, Wm1, bm1);    // kernel 5
    k_edge <<<1184, TB>>>(src, dst, ea, Wm1, Wm2, bm2, out);  // kernel 6
}

// round 14
// speedup vs baseline: 1.5298x; 1.2292x over previous
#include <cuda_runtime.h>
#include <cuda_fp16.h>

#define NN 100000
#define NE 3200000
#define H  64
#define SCAN_B 1024
#define NB 98                      // ceil(NN / SCAN_B)
#define PAD 68                     // 64 + 4: 16B-aligned, conflict-free LDS.128

// -------- device scratch (no allocations allowed) --------
__device__ int     g_cnt[NN];
__device__ int     g_row[NN + 1];
__device__ int     g_pos[NN];
__device__ float   g_dis[NN];
__device__ unsigned long long g_look[NB];   // lookback: status(2b)<<62 | value
__device__ int2    g_e[NE];          // CSR slot: (src, bitcast weight)
__device__ __half2 g_h1h[NN * 32];   // h1 fp16 pairs (cols 2l, 2l+1)
__device__ __half  g_Ph[NN * H];     // fp16: h2 @ Wm1[0:64] + bm1
__device__ __half  g_Qh[NN * H];     // fp16: h2 @ Wm1[64:128]

// -------- 1: histogram of in-degrees --------
__global__ void k_hist(const int* __restrict__ dst) {
    int e = blockIdx.x * blockDim.x + threadIdx.x;
    if (e < NE) atomicAdd(&g_cnt[dst[e]], 1);
}

// -------- 2: single-kernel exclusive scan (decoupled lookback) --------
__global__ void k_scan() {
    __shared__ int ss[SCAN_B];
    __shared__ int s_base;
    int tid = threadIdx.x, bid = blockIdx.x;
    int i = bid * SCAN_B + tid;
    int v = (i < NN) ? g_cnt[i] : 0;
    ss[tid] = v;
    __syncthreads();
#pragma unroll
    for (int off = 1; off < SCAN_B; off <<= 1) {
        int t = (tid >= off) ? ss[tid - off] : 0;
        __syncthreads();
        ss[tid] += t;
        __syncthreads();
    }
    int incl  = ss[tid];
    int total = ss[SCAN_B - 1];
    if (tid == 0) {
        unsigned long long pub = (bid == 0)
            ? ((2ULL << 62) | (unsigned long long)(unsigned)total)
            : ((1ULL << 62) | (unsigned long long)(unsigned)total);
        atomicExch(&g_look[bid], pub);
        int base = 0;
        if (bid > 0) {
            int j = bid - 1;
            while (true) {
                unsigned long long v2;
                do { v2 = atomicOr(&g_look[j], 0ULL); } while ((v2 >> 62) == 0ULL);
                base += (int)(v2 & 0xFFFFFFFFULL);
                if ((v2 >> 62) == 2ULL) break;
                j--;
            }
            atomicExch(&g_look[bid],
                       (2ULL << 62) | (unsigned long long)(unsigned)(base + total));
        }
        s_base = base;
    }
    __syncthreads();
    int base = s_base;
    if (i < NN) {
        int r = incl - v + base;
        g_row[i] = r;
        g_pos[i] = r;
        g_dis[i] = rsqrtf((float)(g_cnt[i] + 1));   // +1 self-loop
    }
    if (i == 0) g_row[NN] = NE;
}

// -------- 3: CSR placement --------
__global__ void k_place(const int* __restrict__ src, const int* __restrict__ dst) {
    int e = blockIdx.x * blockDim.x + threadIdx.x;
    if (e >= NE) return;
    int s = src[e], d = dst[e];
    int idx = atomicAdd(&g_pos[d], 1);
    int2 ev; ev.x = s; ev.y = __float_as_int(g_dis[s] * g_dis[d]);
    g_e[idx] = ev;
}

// -------- 4: fused layer 1: warp per node; h1 out in fp16 pairs --------
__global__ void k_aggx_h1(const float* __restrict__ x,
                          const float* __restrict__ W1, const float* __restrict__ b1) {
    int w = (blockIdx.x * blockDim.x + threadIdx.x) >> 5;
    if (w >= NN) return;
    int lane = threadIdx.x & 31;
    int r0 = g_row[w], r1 = g_row[w + 1];
    float ax = 0.f, ay = 0.f, az = 0.f, aw = 0.f;
#pragma unroll 4
    for (int r = r0 + lane; r < r1; r += 32) {
        int2 ev = g_e[r];
        float ww = __int_as_float(ev.y);
        float4 xv = *reinterpret_cast<const float4*>(x + (size_t)ev.x * 4);
        ax += xv.x * ww; ay += xv.y * ww; az += xv.z * ww; aw += xv.w * ww;
    }
    if (lane == 0) {                     // self-loop
        float dd = g_dis[w]; dd *= dd;
        float4 xv = *reinterpret_cast<const float4*>(x + (size_t)w * 4);
        ax += dd * xv.x; ay += dd * xv.y; az += dd * xv.z; aw += dd * xv.w;
    }
#pragma unroll
    for (int off = 16; off >= 1; off >>= 1) {
        ax += __shfl_xor_sync(0xffffffffu, ax, off);
        ay += __shfl_xor_sync(0xffffffffu, ay, off);
        az += __shfl_xor_sync(0xffffffffu, az, off);
        aw += __shfl_xor_sync(0xffffffffu, aw, off);
    }
    int c0 = 2 * lane, c1 = c0 + 1;
    float s0 = ax * __ldg(W1 + c0) + ay * __ldg(W1 + 64 + c0)
             + az * __ldg(W1 + 128 + c0) + aw * __ldg(W1 + 192 + c0) + __ldg(b1 + c0);
    float s1 = ax * __ldg(W1 + c1) + ay * __ldg(W1 + 64 + c1)
             + az * __ldg(W1 + 128 + c1) + aw * __ldg(W1 + 192 + c1) + __ldg(b1 + c1);
    g_h1h[(size_t)w * 32 + lane] = __floats2half2_rn(fmaxf(s0, 0.f), fmaxf(s1, 0.f));
}

// -------- 5: fused layer-2 agg (edge-balanced) + tiled dense + P,Q --------
// Block: 512 thr = 16 warps, 16 nodes. Stage A: warps split the block's WHOLE
// edge range evenly (CSR is node-sorted, so a warp spans few nodes); per-node
// partials flushed to smem via atomicAdd at segment boundaries. Removes the
// max-degree straggler that stalled the old warp-per-node scheme.
__global__ void k_agg_dense2(const float* __restrict__ W2, const float* __restrict__ b2,
                             const float* __restrict__ Wm1, const float* __restrict__ bm1) {
    __shared__ float sWa[64 * PAD];
    __shared__ float sWb[64 * PAD];
    __shared__ float sIn[16 * PAD];
    __shared__ int   sRow[17];
    int tid  = threadIdx.x;
    int nb   = blockIdx.x * 16;
    int wid  = tid >> 5, lane = tid & 31;

    if (tid < 17) sRow[tid] = g_row[nb + tid];
    for (int i = tid; i < 16 * PAD; i += 512) sIn[i] = 0.f;
    __syncthreads();

    // ---- stage A: balanced edge aggregation ----
    {
        int R0 = sRow[0], R1 = sRow[16];
        int total = R1 - R0;
        int chunk = (total + 15) >> 4;
        int s = R0 + wid * chunk;
        int epos = s + chunk; if (epos > R1) epos = R1;
        if (s < epos) {
            // binary search: largest cur with sRow[cur] <= s
            int lo = 0, hi = 16;
            while (lo < hi) {
                int mid = (lo + hi + 1) >> 1;
                if (sRow[mid] <= s) lo = mid; else hi = mid - 1;
            }
            int cur = lo;
            int r = s;
            while (r < epos) {
                while (r >= sRow[cur + 1]) cur++;
                int seg = sRow[cur + 1]; if (seg > epos) seg = epos;
                float a0 = 0.f, a1 = 0.f;
                for (; r + 3 < seg; r += 4) {
                    int2 ev[4];
#pragma unroll
                    for (int u = 0; u < 4; u++) ev[u] = g_e[r + u];
                    __half2 hv[4];
#pragma unroll
                    for (int u = 0; u < 4; u++) hv[u] = g_h1h[(size_t)ev[u].x * 32 + lane];
#pragma unroll
                    for (int u = 0; u < 4; u++) {
                        float2 v = __half22float2(hv[u]);
                        float we = __int_as_float(ev[u].y);
                        a0 += v.x * we;
                        a1 += v.y * we;
                    }
                }
                for (; r < seg; r++) {
                    int2 ev = g_e[r];
                    float2 v = __half22float2(g_h1h[(size_t)ev.x * 32 + lane]);
                    float we = __int_as_float(ev.y);
                    a0 += v.x * we;
                    a1 += v.y * we;
                }
                atomicAdd(&sIn[cur * PAD + 2 * lane],     a0);
                atomicAdd(&sIn[cur * PAD + 2 * lane + 1], a1);
            }
        }
        // self-loop term: warp wid owns node wid
        int node = nb + wid;
        float dd = g_dis[node]; dd *= dd;
        float2 v = __half22float2(g_h1h[(size_t)node * 32 + lane]);
        atomicAdd(&sIn[wid * PAD + 2 * lane],     v.x * dd);
        atomicAdd(&sIn[wid * PAD + 2 * lane + 1], v.y * dd);
    }
    // W2 transposed into sWa
    for (int i = tid; i < 4096; i += 512)
        sWa[(i & 63) * PAD + (i >> 6)] = W2[i];
    __syncthreads();

    // ---- stage B: h2 = relu(tmp @ W2 + b2), register-tiled ----
    int col = tid & 63, ng = tid >> 6;
    float hreg[2];
    {
        const float4* wp = reinterpret_cast<const float4*>(sWa + col * PAD);
        const float4* i0 = reinterpret_cast<const float4*>(sIn + ng * PAD);
        const float4* i1 = reinterpret_cast<const float4*>(sIn + (ng + 8) * PAD);
        float a0 = 0.f, a1 = 0.f;
#pragma unroll
        for (int k4 = 0; k4 < 16; k4++) {
            float4 w = wp[k4];
            float4 v0 = i0[k4];
            float4 v1 = i1[k4];
            a0 += v0.x * w.x + v0.y * w.y + v0.z * w.z + v0.w * w.w;
            a1 += v1.x * w.x + v1.y * w.y + v1.z * w.z + v1.w * w.w;
        }
        float bb = __ldg(b2 + col);
        hreg[0] = fmaxf(a0 + bb, 0.f);
        hreg[1] = fmaxf(a1 + bb, 0.f);
    }
    __syncthreads();

    // ---- stage C: P,Q = h2 @ Wm1 halves, register-tiled ----
    sIn[ng * PAD + col]       = hreg[0];
    sIn[(ng + 8) * PAD + col] = hreg[1];
    for (int i = tid; i < 4096; i += 512) {
        int k = i >> 6, c = i & 63;
        sWa[c * PAD + k] = Wm1[i];
        sWb[c * PAD + k] = Wm1[4096 + i];
    }
    __syncthreads();
    {
        const float4* wa = reinterpret_cast<const float4*>(sWa + col * PAD);
        const float4* wb = reinterpret_cast<const float4*>(sWb + col * PAD);
        const float4* i0 = reinterpret_cast<const float4*>(sIn + ng * PAD);
        const float4* i1 = reinterpret_cast<const float4*>(sIn + (ng + 8) * PAD);
        float p0 = 0.f, p1 = 0.f, q0 = 0.f, q1 = 0.f;
#pragma unroll
        for (int k4 = 0; k4 < 16; k4++) {
            float4 a = wa[k4];
            float4 b = wb[k4];
            float4 v0 = i0[k4];
            float4 v1 = i1[k4];
            p0 += v0.x * a.x + v0.y * a.y + v0.z * a.z + v0.w * a.w;
            q0 += v0.x * b.x + v0.y * b.y + v0.z * b.z + v0.w * b.w;
            p1 += v1.x * a.x + v1.y * a.y + v1.z * a.z + v1.w * a.w;
            q1 += v1.x * b.x + v1.y * b.y + v1.z * b.z + v1.w * b.w;
        }
        float bmv = __ldg(bm1 + col);
        size_t o0 = (size_t)(nb + ng) * 64 + col;
        size_t o1 = (size_t)(nb + ng + 8) * 64 + col;
        g_Ph[o0] = __float2half(p0 + bmv);
        g_Qh[o0] = __float2half(q0);
        g_Ph[o1] = __float2half(p1 + bmv);
        g_Qh[o1] = __float2half(q1);
    }
}

// -------- 6: edge epilogue, 8 lanes/edge, half2 SIMD math --------
// out[e] = relu(P[s]+Q[d]+ea@Wea) @ Wm2 + bm2
__global__ void k_edge(const int* __restrict__ src, const int* __restrict__ dst,
                       const float* __restrict__ ea,
                       const float* __restrict__ Wm1,
                       const float* __restrict__ Wm2, const float* __restrict__ bm2,
                       float* __restrict__ out) {
    int l  = threadIdx.x & 7;
    int c0 = l * 8;                       // 8 columns per lane
    __half2 wh[4][4];                     // Wea rows k=0..3 at my 8 cols (half2 pairs)
#pragma unroll
    for (int k = 0; k < 4; k++)
#pragma unroll
        for (int j = 0; j < 4; j++)
            wh[k][j] = __floats2half2_rn(__ldg(Wm1 + (128 + k) * 64 + c0 + 2 * j),
                                         __ldg(Wm1 + (128 + k) * 64 + c0 + 2 * j + 1));
    __half2 woh[4];
#pragma unroll
    for (int j = 0; j < 4; j++)
        woh[j] = __floats2half2_rn(__ldg(Wm2 + c0 + 2 * j), __ldg(Wm2 + c0 + 2 * j + 1));
    const __half2 zero2 = __float2half2_rn(0.f);
    float ob = bm2[0];

    int grp  = (blockIdx.x * blockDim.x + threadIdx.x) >> 3;
    int ngrp = (gridDim.x * blockDim.x) >> 3;
    for (int e0 = grp; e0 < NE; e0 += 4 * ngrp) {
        float part[4];
        int   ee[4];
        bool  ok[4];
#pragma unroll
        for (int u = 0; u < 4; u++) {
            int e = e0 + u * ngrp;
            ok[u] = (e < NE);
            ee[u] = ok[u] ? e : e0;
            int s = src[ee[u]], d = dst[ee[u]];
            uint4 pv = *reinterpret_cast<const uint4*>(g_Ph + (size_t)s * 64 + c0);
            uint4 qv = *reinterpret_cast<const uint4*>(g_Qh + (size_t)d * 64 + c0);
            float4 a = *reinterpret_cast<const float4*>(ea + (size_t)ee[u] * 4);
            const __half2* ph = reinterpret_cast<const __half2*>(&pv);
            const __half2* qh = reinterpret_cast<const __half2*>(&qv);
            __half2 eh0 = __float2half2_rn(a.x);
            __half2 eh1 = __float2half2_rn(a.y);
            __half2 eh2 = __float2half2_rn(a.z);
            __half2 eh3 = __float2half2_rn(a.w);
            __half2 acc[4];
#pragma unroll
            for (int j = 0; j < 4; j++) {
                acc[j] = __hadd2(ph[j], qh[j]);
                acc[j] = __hfma2(eh0, wh[0][j], acc[j]);
                acc[j] = __hfma2(eh1, wh[1][j], acc[j]);
                acc[j] = __hfma2(eh2, wh[2][j], acc[j]);
                acc[j] = __hfma2(eh3, wh[3][j], acc[j]);
                acc[j] = __hmax2(acc[j], zero2);
            }
            __half2 t = __hmul2(acc[0], woh[0]);
            t = __hfma2(acc[1], woh[1], t);
            t = __hfma2(acc[2], woh[2], t);
            t = __hfma2(acc[3], woh[3], t);
            part[u] = __low2float(t) + __high2float(t);
        }
#pragma unroll
        for (int off = 4; off >= 1; off >>= 1) {
#pragma unroll
            for (int u = 0; u < 4; u++)
                part[u] += __shfl_down_sync(0xffffffffu, part[u], off, 8);
        }
        if (l == 0) {
#pragma unroll
            for (int u = 0; u < 4; u++)
                if (ok[u]) out[ee[u]] = part[u] + ob;
        }
    }
}

extern "C" void kernel_launch(void* const* d_in, const int* in_sizes, int n_in,
                              void* d_out, int out_size) {
    const float* x   = (const float*)d_in[0];
    const int*   ei  = (const int*)  d_in[1];   // [2, NE] int32
    const float* ea  = (const float*)d_in[2];
    const float* W1  = (const float*)d_in[3];
    const float* b1  = (const float*)d_in[4];
    const float* W2  = (const float*)d_in[5];
    const float* b2  = (const float*)d_in[6];
    const float* Wm1 = (const float*)d_in[7];
    const float* bm1 = (const float*)d_in[8];
    const float* Wm2 = (const float*)d_in[9];
    const float* bm2 = (const float*)d_in[10];
    float* out = (float*)d_out;

    const int* src = ei;
    const int* dst = ei + NE;

    void* p_cnt  = nullptr;
    void* p_look = nullptr;
    cudaGetSymbolAddress(&p_cnt,  g_cnt);
    cudaGetSymbolAddress(&p_look, g_look);
    cudaMemsetAsync(p_cnt,  0, NN * sizeof(int), 0);
    cudaMemsetAsync(p_look, 0, NB * sizeof(unsigned long long), 0);

    const int TB = 256;
    int ne_blk  = (NE + TB - 1) / TB;
    int agg_blk = (NN + 7) / 8;

    k_hist <<<ne_blk, TB>>>(dst);                        // kernel 1
    k_scan <<<NB, SCAN_B>>>();                           // kernel 2
    k_place<<<ne_blk, TB>>>(src, dst);                   // kernel 3
    k_aggx_h1<<<agg_blk, TB>>>(x, W1, b1);               // kernel 4 (capture slot)
    k_agg_dense2<<<NN / 16, 512>>>(W2, b2, Wm1, bm1);    // kernel 5
    k_edge <<<1184, TB>>>(src, dst, ea, Wm1, Wm2, bm2, out);  // kernel 6
}